// round 9
// baseline (speedup 1.0000x reference)
#include <cuda_runtime.h>
#include <math.h>
#include <stdint.h>

// Problem constants
#define BB 2
#define SS 4096
#define FF 768
#define HH 12
#define DD 64
#define MM (BB * SS)       // 8192
#define NQKV (3 * FF)      // 2304

// Scratch (allocation-free rule: __device__ globals)
__device__ float g_qkv[(size_t)MM * NQKV];   // [B*S, 3F]
__device__ float g_att[(size_t)MM * FF];     // [B*S, F]

// ---------------------------------------------------------------------------
// tf32 helpers. cvt.rna (round-to-nearest) is REQUIRED: bit-truncation to tf32
// is biased toward zero and the bias accumulates linearly over K.
// ---------------------------------------------------------------------------
__device__ __forceinline__ unsigned f2tf(float x) {
    unsigned u;
    asm("cvt.rna.tf32.f32 %0, %1;" : "=r"(u) : "f"(x));
    return u;
}
__device__ __forceinline__ float f2tff(float x) { return __uint_as_float(f2tf(x)); }

// D(16x8) += A(16x8,row) * B(8x8,col), tf32 inputs, fp32 accum.
__device__ __forceinline__ void mma8(float d[4], const unsigned a[4],
                                     unsigned b0, unsigned b1) {
    asm volatile(
        "mma.sync.aligned.m16n8k8.row.col.f32.tf32.tf32.f32 "
        "{%0,%1,%2,%3},{%4,%5,%6,%7},{%8,%9},{%0,%1,%2,%3};"
        : "+f"(d[0]), "+f"(d[1]), "+f"(d[2]), "+f"(d[3])
        : "r"(a[0]), "r"(a[1]), "r"(a[2]), "r"(a[3]), "r"(b0), "r"(b1));
}

// ---------------------------------------------------------------------------
// GEMM + bias, tf32 tensor-core, 2-stage smem pipeline with register-staged
// LDG prefetch. 128x128 CTA tile, 8 warps (4m x 2n), k-chunk 16.
// One __syncthreads per chunk: the stage overwritten at iter k's tail was
// last read at iter k-1, and every warp passed iter k-1's tail barrier
// before starting iter k's compute.
// ---------------------------------------------------------------------------
#define AST 20
#define BST 136
#define ASZ (128 * AST)
#define BSZ (16 * BST)
__global__ __launch_bounds__(256, 2) void gemm_tf32_kernel(
    const float* __restrict__ A, const float* __restrict__ W,
    const float* __restrict__ bias, float* __restrict__ C,
    int M, int N, int K)
{
    __shared__ float As[2 * ASZ];   // [stage][m][k] tf32-rounded
    __shared__ float Bs[2 * BSZ];   // [stage][k][n] tf32-rounded

    const int tid = threadIdx.x;
    const int wid = tid >> 5, lane = tid & 31;
    const int g = lane >> 2, tig = lane & 3;
    const int wm = (wid >> 1) * 32;
    const int wn = (wid & 1) * 64;
    const int row0 = blockIdx.y * 128;
    const int col0 = blockIdx.x * 128;

    float4 areg[2], breg[2];
    auto LDG = [&](int k0) {
#pragma unroll
        for (int l = 0; l < 2; l++) {
            int id = tid + l * 256;
            int ar = id >> 2, ac = id & 3;
            areg[l] = *(const float4*)(A + (size_t)(row0 + ar) * K + k0 + ac * 4);
            int br = id >> 5, bc = id & 31;
            breg[l] = *(const float4*)(W + (size_t)(k0 + br) * N + col0 + bc * 4);
        }
    };
    auto STS = [&](int st) {
        float* ap = As + st * ASZ;
        float* bp = Bs + st * BSZ;
#pragma unroll
        for (int l = 0; l < 2; l++) {
            int id = tid + l * 256;
            int ar = id >> 2, ac = id & 3;
            float4 t;
            t.x = f2tff(areg[l].x); t.y = f2tff(areg[l].y);
            t.z = f2tff(areg[l].z); t.w = f2tff(areg[l].w);
            *(float4*)(ap + ar * AST + ac * 4) = t;
            int br = id >> 5, bc = id & 31;
            float4 u;
            u.x = f2tff(breg[l].x); u.y = f2tff(breg[l].y);
            u.z = f2tff(breg[l].z); u.w = f2tff(breg[l].w);
            *(float4*)(bp + br * BST + bc * 4) = u;
        }
    };

    float acc[2][8][4];
#pragma unroll
    for (int mt = 0; mt < 2; mt++)
#pragma unroll
        for (int nt = 0; nt < 8; nt++)
#pragma unroll
            for (int c = 0; c < 4; c++) acc[mt][nt][c] = 0.f;

    const int nk = K >> 4;
    LDG(0);
    STS(0);
    if (nk > 1) LDG(16);
    __syncthreads();

    for (int ki = 0; ki < nk; ki++) {
        const int st = ki & 1;
        const float* ap = As + st * ASZ;
        const float* bp = Bs + st * BSZ;

#pragma unroll
        for (int ks = 0; ks < 16; ks += 8) {
            unsigned a[2][4];
#pragma unroll
            for (int mt = 0; mt < 2; mt++) {
                int rbse = wm + mt * 16;
                a[mt][0] = __float_as_uint(ap[(rbse + g) * AST + ks + tig]);
                a[mt][1] = __float_as_uint(ap[(rbse + g + 8) * AST + ks + tig]);
                a[mt][2] = __float_as_uint(ap[(rbse + g) * AST + ks + tig + 4]);
                a[mt][3] = __float_as_uint(ap[(rbse + g + 8) * AST + ks + tig + 4]);
            }
#pragma unroll
            for (int nt = 0; nt < 8; nt++) {
                unsigned b0 = __float_as_uint(bp[(ks + tig) * BST + wn + nt * 8 + g]);
                unsigned b1 = __float_as_uint(bp[(ks + tig + 4) * BST + wn + nt * 8 + g]);
                mma8(acc[0][nt], a[0], b0, b1);
                mma8(acc[1][nt], a[1], b0, b1);
            }
        }

        if (ki + 1 < nk) {
            STS(st ^ 1);                     // safe: stage st^1 idle since iter ki-1
            if (ki + 2 < nk) LDG((ki + 2) << 4);  // in flight through next compute
            __syncthreads();
        }
    }

#pragma unroll
    for (int mt = 0; mt < 2; mt++) {
        int r0 = row0 + wm + mt * 16 + g;
#pragma unroll
        for (int nt = 0; nt < 8; nt++) {
            int c = col0 + wn + nt * 8 + 2 * tig;
            float bx = bias[c], by = bias[c + 1];
            *(float2*)(C + (size_t)r0 * N + c) =
                make_float2(acc[mt][nt][0] + bx, acc[mt][nt][1] + by);
            *(float2*)(C + (size_t)(r0 + 8) * N + c) =
                make_float2(acc[mt][nt][2] + bx, acc[mt][nt][3] + by);
        }
    }
}

// ---------------------------------------------------------------------------
// Flash attention, tf32 tensor-core, 2-stage K/V pipeline.
// 128-query x 64-key blocks, 8 warps, warp owns m16 x n64.
// ONE __syncthreads per key-block (pipeline argument as in the GEMM);
// P bounce is warp-private rows -> __syncwarp only.
// Dynamic smem: (4*64*68 + 128*68)*4 + 128 = 104576 B.
// ---------------------------------------------------------------------------
#define KVSZ (64 * 68)
__global__ __launch_bounds__(256, 1) void attn_tf32_kernel(
    const float* __restrict__ qkv, const unsigned char* __restrict__ mask,
    float* __restrict__ att)
{
    extern __shared__ float sm[];
    float* Ks = sm;                       // 2 stages [64 key][68] (d inner)
    float* Vt = sm + 2 * KVSZ;            // 2 stages [64 d][68]   (key inner)
    float* Ps = sm + 4 * KVSZ;            // [128 q][68]           (key inner)
    unsigned char* msk = (unsigned char*)(sm + 4 * KVSZ + 128 * 68);  // 2 x 64

    const int qb = gridDim.x - 1 - blockIdx.x;   // big blocks first (balance)
    const int h = blockIdx.y, b = blockIdx.z;
    const int tid = threadIdx.x;
    const int wid = tid >> 5, lane = tid & 31;
    const int g = lane >> 2, tig = lane & 3;
    const int m0 = wid * 16;
    const int q0 = qb * 128;
    const size_t rb = (size_t)b * SS;
    const int qr0 = q0 + m0 + g;
    const int qr1 = qr0 + 8;

    float4 kreg[4], vreg[4];
    unsigned char mreg = 0;
    auto ldg_kv = [&](int kb) {
        const float* base = qkv + (rb + (size_t)kb * 64) * NQKV + FF + h * DD;
#pragma unroll
        for (int l = 0; l < 4; l++) {
            int id = tid + l * 256;
            int r = id >> 4, c = id & 15;
            const float* kp = base + (size_t)r * NQKV + c * 4;
            kreg[l] = *(const float4*)kp;
            vreg[l] = *(const float4*)(kp + FF);   // V = K + F
        }
        if (tid < 64) mreg = mask[rb + kb * 64 + tid];
    };
    auto sts_kv = [&](int st) {
        float* ksp = Ks + st * KVSZ;
        float* vtp = Vt + st * KVSZ;
#pragma unroll
        for (int l = 0; l < 4; l++) {
            int id = tid + l * 256;
            int r = id >> 4, c = id & 15;
            float4 kt;
            kt.x = f2tff(kreg[l].x); kt.y = f2tff(kreg[l].y);
            kt.z = f2tff(kreg[l].z); kt.w = f2tff(kreg[l].w);
            *(float4*)(ksp + r * 68 + c * 4) = kt;
            vtp[(c * 4 + 0) * 68 + r] = f2tff(vreg[l].x);
            vtp[(c * 4 + 1) * 68 + r] = f2tff(vreg[l].y);
            vtp[(c * 4 + 2) * 68 + r] = f2tff(vreg[l].z);
            vtp[(c * 4 + 3) * 68 + r] = f2tff(vreg[l].w);
        }
        if (tid < 64) msk[st * 64 + tid] = mreg;
    };

    // Q fragments (pre-scaled by 1/sqrt(D), tf32-rounded), resident all kernel
    unsigned qf[8][4];
    {
        const float* p0 = qkv + (rb + qr0) * NQKV + h * DD;
        const float* p1 = p0 + (size_t)8 * NQKV;
#pragma unroll
        for (int kk = 0; kk < 8; kk++) {
            qf[kk][0] = f2tf(p0[kk * 8 + tig] * 0.125f);
            qf[kk][1] = f2tf(p1[kk * 8 + tig] * 0.125f);
            qf[kk][2] = f2tf(p0[kk * 8 + tig + 4] * 0.125f);
            qf[kk][3] = f2tf(p1[kk * 8 + tig + 4] * 0.125f);
        }
    }

    float m_i[2] = {-INFINITY, -INFINITY};
    float l_i[2] = {0.f, 0.f};
    float oacc[8][4];
#pragma unroll
    for (int nt = 0; nt < 8; nt++)
#pragma unroll
        for (int c = 0; c < 4; c++) oacc[nt][c] = 0.f;

    const int nkb = 2 * qb + 2;
    ldg_kv(0);
    sts_kv(0);
    ldg_kv(1);          // nkb >= 2 always
    __syncthreads();

    for (int kb = 0; kb < nkb; kb++) {
        const int st = kb & 1;
        const float* ksp = Ks + st * KVSZ;
        const float* vtp = Vt + st * KVSZ;
        const unsigned char* mp = msk + st * 64;
        const int k0 = kb * 64;

        // S = Q @ K^T
        float sacc[8][4];
#pragma unroll
        for (int nt = 0; nt < 8; nt++)
#pragma unroll
            for (int c = 0; c < 4; c++) sacc[nt][c] = 0.f;
#pragma unroll
        for (int kk = 0; kk < 8; kk++) {
#pragma unroll
            for (int nt = 0; nt < 8; nt++) {
                unsigned b0 = __float_as_uint(ksp[(nt * 8 + g) * 68 + kk * 8 + tig]);
                unsigned b1 = __float_as_uint(ksp[(nt * 8 + g) * 68 + kk * 8 + tig + 4]);
                mma8(sacc[nt], qf[kk], b0, b1);
            }
        }

        // Causal + padding masks
        const bool dcheck = (k0 + 63 > qr0);
#pragma unroll
        for (int nt = 0; nt < 8; nt++) {
            int c0 = k0 + nt * 8 + 2 * tig;
            bool p0 = mp[nt * 8 + 2 * tig] != 0;
            bool p1 = mp[nt * 8 + 2 * tig + 1] != 0;
            if (p0 || (dcheck && c0 > qr0))     sacc[nt][0] = -INFINITY;
            if (p1 || (dcheck && c0 + 1 > qr0)) sacc[nt][1] = -INFINITY;
            if (p0 || (dcheck && c0 > qr1))     sacc[nt][2] = -INFINITY;
            if (p1 || (dcheck && c0 + 1 > qr1)) sacc[nt][3] = -INFINITY;
        }

        // Online softmax (row stats within the quad: 2 shfl_xor)
#pragma unroll
        for (int r = 0; r < 2; r++) {
            float mx = -INFINITY;
#pragma unroll
            for (int nt = 0; nt < 8; nt++)
                mx = fmaxf(mx, fmaxf(sacc[nt][2 * r], sacc[nt][2 * r + 1]));
            mx = fmaxf(mx, __shfl_xor_sync(0xffffffffu, mx, 1));
            mx = fmaxf(mx, __shfl_xor_sync(0xffffffffu, mx, 2));
            float mnew = fmaxf(m_i[r], mx);
            float alpha = __expf(m_i[r] - mnew);
            float sum = 0.f;
#pragma unroll
            for (int nt = 0; nt < 8; nt++) {
                float e0 = __expf(sacc[nt][2 * r] - mnew);
                float e1 = __expf(sacc[nt][2 * r + 1] - mnew);
                sacc[nt][2 * r] = e0;
                sacc[nt][2 * r + 1] = e1;
                sum += e0 + e1;
            }
            sum += __shfl_xor_sync(0xffffffffu, sum, 1);
            sum += __shfl_xor_sync(0xffffffffu, sum, 2);
            l_i[r] = l_i[r] * alpha + sum;
            m_i[r] = mnew;
#pragma unroll
            for (int nt = 0; nt < 8; nt++) {
                oacc[nt][2 * r] *= alpha;
                oacc[nt][2 * r + 1] *= alpha;
            }
        }

        // P bounce: warp-private rows, warp-level sync only
#pragma unroll
        for (int nt = 0; nt < 8; nt++) {
            *(float2*)(Ps + (m0 + g) * 68 + nt * 8 + 2 * tig) =
                make_float2(f2tff(sacc[nt][0]), f2tff(sacc[nt][1]));
            *(float2*)(Ps + (m0 + g + 8) * 68 + nt * 8 + 2 * tig) =
                make_float2(f2tff(sacc[nt][2]), f2tff(sacc[nt][3]));
        }
        __syncwarp();

        // O += P @ V
#pragma unroll
        for (int kk = 0; kk < 8; kk++) {
            unsigned a[4];
            a[0] = __float_as_uint(Ps[(m0 + g) * 68 + kk * 8 + tig]);
            a[1] = __float_as_uint(Ps[(m0 + g + 8) * 68 + kk * 8 + tig]);
            a[2] = __float_as_uint(Ps[(m0 + g) * 68 + kk * 8 + tig + 4]);
            a[3] = __float_as_uint(Ps[(m0 + g + 8) * 68 + kk * 8 + tig + 4]);
#pragma unroll
            for (int nt = 0; nt < 8; nt++) {
                unsigned b0 = __float_as_uint(vtp[(nt * 8 + g) * 68 + kk * 8 + tig]);
                unsigned b1 = __float_as_uint(vtp[(nt * 8 + g) * 68 + kk * 8 + tig + 4]);
                mma8(oacc[nt], a, b0, b1);
            }
        }

        if (kb + 1 < nkb) {
            sts_kv(st ^ 1);                 // stage st^1 idle since iter kb-1
            if (kb + 2 < nkb) ldg_kv(kb + 2);   // in flight through next compute
            __syncthreads();
        }
    }

    // Epilogue: O / l -> att[B*S, F]
    const float inv0 = 1.f / l_i[0];
    const float inv1 = 1.f / l_i[1];
#pragma unroll
    for (int nt = 0; nt < 8; nt++) {
        int c = h * DD + nt * 8 + 2 * tig;
        *(float2*)(att + (rb + qr0) * FF + c) =
            make_float2(oacc[nt][0] * inv0, oacc[nt][1] * inv0);
        *(float2*)(att + (rb + qr1) * FF + c) =
            make_float2(oacc[nt][2] * inv1, oacc[nt][3] * inv1);
    }
}

// ---------------------------------------------------------------------------
// Launch
// ---------------------------------------------------------------------------
extern "C" void kernel_launch(void* const* d_in, const int* in_sizes, int n_in,
                              void* d_out, int out_size)
{
    (void)in_sizes; (void)n_in; (void)out_size;
    const float*         x    = (const float*)d_in[0];
    const unsigned char* mask = (const unsigned char*)d_in[1];
    const float*         Wqkv = (const float*)d_in[2];
    const float*         bqkv = (const float*)d_in[3];
    const float*         Wout = (const float*)d_in[4];
    const float*         bout = (const float*)d_in[5];
    float*               out  = (float*)d_out;

    void* p;
    cudaGetSymbolAddress(&p, g_qkv);
    float* qkv = (float*)p;
    cudaGetSymbolAddress(&p, g_att);
    float* att = (float*)p;

    // 1) QKV projection
    dim3 g1(NQKV / 128, MM / 128);   // (18, 64)
    gemm_tf32_kernel<<<g1, 256>>>(x, Wqkv, bqkv, qkv, MM, NQKV, FF);

    // 2) Causal flash attention (tf32 MMA, pipelined)
    const int smem = (4 * KVSZ + 128 * 68) * (int)sizeof(float) + 128;  // 104576
    cudaFuncSetAttribute(attn_tf32_kernel,
                         cudaFuncAttributeMaxDynamicSharedMemorySize, smem);
    attn_tf32_kernel<<<dim3(SS / 128, HH, BB), 256, smem>>>(qkv, mask, att);

    // 3) Output projection
    dim3 g2(FF / 128, MM / 128);     // (6, 64)
    gemm_tf32_kernel<<<g2, 256>>>(att, Wout, bout, out, MM, FF, FF);
}

// round 11
// speedup vs baseline: 1.4700x; 1.4700x over previous
#include <cuda_runtime.h>
#include <math.h>
#include <stdint.h>

// Problem constants
#define BB 2
#define SS 4096
#define FF 768
#define HH 12
#define DD 64
#define MM (BB * SS)       // 8192
#define NQKV (3 * FF)      // 2304

// Scratch (allocation-free rule: __device__ globals)
__device__ float g_qkv[(size_t)MM * NQKV];   // [B*S, 3F]
__device__ float g_att[(size_t)MM * FF];     // [B*S, F]

// ---------------------------------------------------------------------------
// Helpers
// ---------------------------------------------------------------------------
__device__ __forceinline__ unsigned f2tf(float x) {   // round-to-nearest tf32
    unsigned u;
    asm("cvt.rna.tf32.f32 %0, %1;" : "=r"(u) : "f"(x));
    return u;
}
__device__ __forceinline__ float f2tff(float x) { return __uint_as_float(f2tf(x)); }
__device__ __forceinline__ float ex2(float x) {       // 2^x (MUFU.EX2)
    float y;
    asm("ex2.approx.f32 %0, %1;" : "=f"(y) : "f"(x));
    return y;
}
__device__ __forceinline__ void mma8(float d[4], const unsigned a[4],
                                     unsigned b0, unsigned b1) {
    asm volatile(
        "mma.sync.aligned.m16n8k8.row.col.f32.tf32.tf32.f32 "
        "{%0,%1,%2,%3},{%4,%5,%6,%7},{%8,%9},{%0,%1,%2,%3};"
        : "+f"(d[0]), "+f"(d[1]), "+f"(d[2]), "+f"(d[3])
        : "r"(a[0]), "r"(a[1]), "r"(a[2]), "r"(a[3]), "r"(b0), "r"(b1));
}
// cp.async: 16B bulk (cg = L1-bypass) and 4B (ca)
__device__ __forceinline__ void cpa16(uint32_t s, const void* g) {
    asm volatile("cp.async.cg.shared.global [%0], [%1], 16;" :: "r"(s), "l"(g));
}
__device__ __forceinline__ void cpa4(uint32_t s, const void* g) {
    asm volatile("cp.async.ca.shared.global [%0], [%1], 4;" :: "r"(s), "l"(g));
}
__device__ __forceinline__ void cp_commit() {
    asm volatile("cp.async.commit_group;");
}
template <int N>
__device__ __forceinline__ void cp_wait() {
    asm volatile("cp.async.wait_group %0;" :: "n"(N));
}

// ---------------------------------------------------------------------------
// GEMM + bias, tf32 MMA, 3-stage cp.async pipeline, in-place tf32 convert.
// 128x128 CTA tile, 8 warps (4m x 2n), k-chunk 16.
// Commit every iteration (possibly empty group) so group numbering is uniform
// and wait_group 1 always means "tile ki has landed".
// Dynamic smem: 3 * (128*20 + 16*136) * 4 = 56832 B.
// ---------------------------------------------------------------------------
#define GAST 20
#define GBST 136
#define GASZ (128 * GAST)       // 2560 floats
#define GBSZ (16 * GBST)        // 2176 floats
#define GSTG (GASZ + GBSZ)      // 4736 floats per stage
__global__ __launch_bounds__(256, 2) void gemm_tf32_kernel(
    const float* __restrict__ A, const float* __restrict__ W,
    const float* __restrict__ bias, float* __restrict__ C,
    int M, int N, int K)
{
    extern __shared__ float gs[];
    const uint32_t sbase = (uint32_t)__cvta_generic_to_shared(gs);

    const int tid = threadIdx.x;
    const int wid = tid >> 5, lane = tid & 31;
    const int g = lane >> 2, tig = lane & 3;
    const int wm = (wid >> 1) * 32;
    const int wn = (wid & 1) * 64;
    const int row0 = blockIdx.y * 128;
    const int col0 = blockIdx.x * 128;

    auto issue = [&](int t) {   // async-copy tile t (raw fp32) into stage t%3
        const uint32_t sb = sbase + (uint32_t)((t % 3) * GSTG) * 4u;
#pragma unroll
        for (int l = 0; l < 2; l++) {
            int id = tid + l * 256;
            int ar = id >> 2, ac = id & 3;
            cpa16(sb + (uint32_t)(ar * GAST + ac * 4) * 4u,
                  A + (size_t)(row0 + ar) * K + t * 16 + ac * 4);
            int br = id >> 5, bc = id & 31;
            cpa16(sb + (uint32_t)(GASZ + br * GBST + bc * 4) * 4u,
                  W + (size_t)(t * 16 + br) * N + col0 + bc * 4);
        }
    };
    auto convert = [&](int s) {   // in-place cvt.rna of stage s
        float* ap = gs + s * GSTG;
        float* bp = ap + GASZ;
#pragma unroll
        for (int l = 0; l < 2; l++) {
            int id = tid + l * 256;
            int ar = id >> 2, ac = id & 3;
            float4* pa = (float4*)(ap + ar * GAST + ac * 4);
            float4 va = *pa;
            va.x = f2tff(va.x); va.y = f2tff(va.y);
            va.z = f2tff(va.z); va.w = f2tff(va.w);
            *pa = va;
            int br = id >> 5, bc = id & 31;
            float4* pb = (float4*)(bp + br * GBST + bc * 4);
            float4 vb = *pb;
            vb.x = f2tff(vb.x); vb.y = f2tff(vb.y);
            vb.z = f2tff(vb.z); vb.w = f2tff(vb.w);
            *pb = vb;
        }
    };

    float acc[2][8][4];
#pragma unroll
    for (int mt = 0; mt < 2; mt++)
#pragma unroll
        for (int nt = 0; nt < 8; nt++)
#pragma unroll
            for (int c = 0; c < 4; c++) acc[mt][nt][c] = 0.f;

    const int nk = K >> 4;
    issue(0); cp_commit();
    if (nk > 1) issue(1);
    cp_commit();

    for (int ki = 0; ki < nk; ki++) {
        cp_wait<1>();          // tile ki landed (newest group = tile ki+1)
        __syncthreads();
        const int st = ki % 3;
        convert(st);
        __syncthreads();

        const float* ap = gs + st * GSTG;
        const float* bp = ap + GASZ;
#pragma unroll
        for (int ks = 0; ks < 16; ks += 8) {
            unsigned a[2][4];
#pragma unroll
            for (int mt = 0; mt < 2; mt++) {
                int rbse = wm + mt * 16;
                a[mt][0] = __float_as_uint(ap[(rbse + g) * GAST + ks + tig]);
                a[mt][1] = __float_as_uint(ap[(rbse + g + 8) * GAST + ks + tig]);
                a[mt][2] = __float_as_uint(ap[(rbse + g) * GAST + ks + tig + 4]);
                a[mt][3] = __float_as_uint(ap[(rbse + g + 8) * GAST + ks + tig + 4]);
            }
#pragma unroll
            for (int nt = 0; nt < 8; nt++) {
                unsigned b0 = __float_as_uint(bp[(ks + tig) * GBST + wn + nt * 8 + g]);
                unsigned b1 = __float_as_uint(bp[(ks + tig + 4) * GBST + wn + nt * 8 + g]);
                mma8(acc[0][nt], a[0], b0, b1);
                mma8(acc[1][nt], a[1], b0, b1);
            }
        }

        // Prefetch tile ki+2 into stage (ki-1)%3 — idle since the top barrier.
        if (ki + 2 < nk) issue(ki + 2);
        cp_commit();           // always commit: uniform group numbering
    }

#pragma unroll
    for (int mt = 0; mt < 2; mt++) {
        int r0 = row0 + wm + mt * 16 + g;
#pragma unroll
        for (int nt = 0; nt < 8; nt++) {
            int c = col0 + wn + nt * 8 + 2 * tig;
            float bx = bias[c], by = bias[c + 1];
            *(float2*)(C + (size_t)r0 * N + c) =
                make_float2(acc[mt][nt][0] + bx, acc[mt][nt][1] + by);
            *(float2*)(C + (size_t)(r0 + 8) * N + c) =
                make_float2(acc[mt][nt][2] + bx, acc[mt][nt][3] + by);
        }
    }
}

// ---------------------------------------------------------------------------
// Flash attention, tf32 MMA, 3-stage cp.async K/V pipeline.
// 128q x 64k blocks, 8 warps, warp owns m16 x n64.
// K stored [key][d] stride 68 (QK b-frags conflict-free: 68 % 32 == 4);
// V stored [key][d] stride 72 (PV b-frags conflict-free: 72 % 32 == 8) —
// NO transpose needed anymore. In-place tf32 convert pass per tile.
// Softmax in log2 domain (log2e folded into Q scale), raw MUFU.EX2.
// Dynamic smem: 3*(64*68+64*72)*4 + 128*68*4 + 3*64 = 142528 B.
// ---------------------------------------------------------------------------
#define KST 68
#define VST 72
#define KSZ (64 * KST)          // 4352 floats
#define VSZ (64 * VST)          // 4608 floats
#define STG (KSZ + VSZ)         // 8960 floats per stage
#define PSOFF (3 * STG)         // Ps offset (floats)
#define MSKOFF (PSOFF + 128 * 68)
__global__ __launch_bounds__(256, 1) void attn_tf32_kernel(
    const float* __restrict__ qkv, const unsigned char* __restrict__ mask,
    float* __restrict__ att)
{
    extern __shared__ float sm[];
    float* Ps = sm + PSOFF;                       // [128 q][68] (key inner)
    unsigned char* msk = (unsigned char*)(sm + MSKOFF);  // 3 x 64
    const uint32_t sbase = (uint32_t)__cvta_generic_to_shared(sm);

    const int qb = gridDim.x - 1 - blockIdx.x;    // big blocks first (balance)
    const int h = blockIdx.y, b = blockIdx.z;
    const int tid = threadIdx.x;
    const int wid = tid >> 5, lane = tid & 31;
    const int g = lane >> 2, tig = lane & 3;
    const int m0 = wid * 16;
    const int q0 = qb * 128;
    const size_t rb = (size_t)b * SS;
    const int qr0 = q0 + m0 + g;
    const int qr1 = qr0 + 8;

    auto issue = [&](int kb) {   // async-copy K/V tile kb + mask into stage kb%3
        const int s = kb % 3;
        const uint32_t sb = sbase + (uint32_t)(s * STG) * 4u;
        const float* base = qkv + (rb + (size_t)kb * 64) * NQKV + FF + h * DD;
#pragma unroll
        for (int l = 0; l < 4; l++) {
            int id = tid + l * 256;
            int r = id >> 4, c = id & 15;
            const float* kp = base + (size_t)r * NQKV + c * 4;
            cpa16(sb + (uint32_t)(r * KST + c * 4) * 4u, kp);
            cpa16(sb + (uint32_t)(KSZ + r * VST + c * 4) * 4u, kp + FF);  // V = K + F
        }
        if (tid < 16)
            cpa4(sbase + (uint32_t)MSKOFF * 4u + (uint32_t)(s * 64 + tid * 4),
                 mask + rb + (size_t)kb * 64 + tid * 4);
    };
    auto convert = [&](int s) {   // in-place cvt.rna of stage s (K and V)
        float* ksp = sm + s * STG;
        float* vsp = ksp + KSZ;
#pragma unroll
        for (int l = 0; l < 4; l++) {
            int id = tid + l * 256;
            int r = id >> 4, c = id & 15;
            float4* pk = (float4*)(ksp + r * KST + c * 4);
            float4 vk = *pk;
            vk.x = f2tff(vk.x); vk.y = f2tff(vk.y);
            vk.z = f2tff(vk.z); vk.w = f2tff(vk.w);
            *pk = vk;
            float4* pv = (float4*)(vsp + r * VST + c * 4);
            float4 vv = *pv;
            vv.x = f2tff(vv.x); vv.y = f2tff(vv.y);
            vv.z = f2tff(vv.z); vv.w = f2tff(vv.w);
            *pv = vv;
        }
    };

    // Q fragments: scale = 1/sqrt(D) * log2(e) (softmax runs in log2 domain)
    const float qscale = 0.125f * 1.44269504f;
    unsigned qf[8][4];
    {
        const float* p0 = qkv + (rb + qr0) * NQKV + h * DD;
        const float* p1 = p0 + (size_t)8 * NQKV;
#pragma unroll
        for (int kk = 0; kk < 8; kk++) {
            qf[kk][0] = f2tf(p0[kk * 8 + tig] * qscale);
            qf[kk][1] = f2tf(p1[kk * 8 + tig] * qscale);
            qf[kk][2] = f2tf(p0[kk * 8 + tig + 4] * qscale);
            qf[kk][3] = f2tf(p1[kk * 8 + tig + 4] * qscale);
        }
    }

    float m_i[2] = {-INFINITY, -INFINITY};
    float l_i[2] = {0.f, 0.f};
    float oacc[8][4];
#pragma unroll
    for (int nt = 0; nt < 8; nt++)
#pragma unroll
        for (int c = 0; c < 4; c++) oacc[nt][c] = 0.f;

    const int nkb = 2 * qb + 2;   // always >= 2
    issue(0); cp_commit();
    issue(1); cp_commit();

    for (int kb = 0; kb < nkb; kb++) {
        cp_wait<1>();             // tile kb landed
        __syncthreads();
        const int st = kb % 3;
        convert(st);
        __syncthreads();

        const float* ksp = sm + st * STG;
        const float* vsp = ksp + KSZ;
        const unsigned char* mp = msk + st * 64;
        const int k0 = kb * 64;

        // S = Q @ K^T (contraction over d)
        float sacc[8][4];
#pragma unroll
        for (int nt = 0; nt < 8; nt++)
#pragma unroll
            for (int c = 0; c < 4; c++) sacc[nt][c] = 0.f;
#pragma unroll
        for (int kk = 0; kk < 8; kk++) {
#pragma unroll
            for (int nt = 0; nt < 8; nt++) {
                unsigned b0 = __float_as_uint(ksp[(nt * 8 + g) * KST + kk * 8 + tig]);
                unsigned b1 = __float_as_uint(ksp[(nt * 8 + g) * KST + kk * 8 + tig + 4]);
                mma8(sacc[nt], qf[kk], b0, b1);
            }
        }

        // Causal + padding masks
        const bool dcheck = (k0 + 63 > qr0);
#pragma unroll
        for (int nt = 0; nt < 8; nt++) {
            int c0 = k0 + nt * 8 + 2 * tig;
            bool p0 = mp[nt * 8 + 2 * tig] != 0;
            bool p1 = mp[nt * 8 + 2 * tig + 1] != 0;
            if (p0 || (dcheck && c0 > qr0))     sacc[nt][0] = -INFINITY;
            if (p1 || (dcheck && c0 + 1 > qr0)) sacc[nt][1] = -INFINITY;
            if (p0 || (dcheck && c0 > qr1))     sacc[nt][2] = -INFINITY;
            if (p1 || (dcheck && c0 + 1 > qr1)) sacc[nt][3] = -INFINITY;
        }

        // Online softmax in log2 domain (quad shuffles)
#pragma unroll
        for (int r = 0; r < 2; r++) {
            float mx = -INFINITY;
#pragma unroll
            for (int nt = 0; nt < 8; nt++)
                mx = fmaxf(mx, fmaxf(sacc[nt][2 * r], sacc[nt][2 * r + 1]));
            mx = fmaxf(mx, __shfl_xor_sync(0xffffffffu, mx, 1));
            mx = fmaxf(mx, __shfl_xor_sync(0xffffffffu, mx, 2));
            float mnew = fmaxf(m_i[r], mx);
            float alpha = ex2(m_i[r] - mnew);   // 0 on first block
            float sum = 0.f;
#pragma unroll
            for (int nt = 0; nt < 8; nt++) {
                float e0 = ex2(sacc[nt][2 * r] - mnew);
                float e1 = ex2(sacc[nt][2 * r + 1] - mnew);
                sacc[nt][2 * r] = e0;
                sacc[nt][2 * r + 1] = e1;
                sum += e0 + e1;
            }
            sum += __shfl_xor_sync(0xffffffffu, sum, 1);
            sum += __shfl_xor_sync(0xffffffffu, sum, 2);
            l_i[r] = l_i[r] * alpha + sum;
            m_i[r] = mnew;
#pragma unroll
            for (int nt = 0; nt < 8; nt++) {
                oacc[nt][2 * r] *= alpha;
                oacc[nt][2 * r + 1] *= alpha;
            }
        }

        // P bounce (tf32-rounded at store): warp-private rows -> __syncwarp
#pragma unroll
        for (int nt = 0; nt < 8; nt++) {
            *(float2*)(Ps + (m0 + g) * 68 + nt * 8 + 2 * tig) =
                make_float2(f2tff(sacc[nt][0]), f2tff(sacc[nt][1]));
            *(float2*)(Ps + (m0 + g + 8) * 68 + nt * 8 + 2 * tig) =
                make_float2(f2tff(sacc[nt][2]), f2tff(sacc[nt][3]));
        }
        __syncwarp();

        // O += P @ V (contraction over keys; V is [key][d], stride 72)
#pragma unroll
        for (int kk = 0; kk < 8; kk++) {
            unsigned a[4];
            a[0] = __float_as_uint(Ps[(m0 + g) * 68 + kk * 8 + tig]);
            a[1] = __float_as_uint(Ps[(m0 + g + 8) * 68 + kk * 8 + tig]);
            a[2] = __float_as_uint(Ps[(m0 + g) * 68 + kk * 8 + tig + 4]);
            a[3] = __float_as_uint(Ps[(m0 + g + 8) * 68 + kk * 8 + tig + 4]);
#pragma unroll
            for (int nt = 0; nt < 8; nt++) {
                unsigned b0 = __float_as_uint(vsp[(kk * 8 + tig) * VST + nt * 8 + g]);
                unsigned b1 = __float_as_uint(vsp[(kk * 8 + tig + 4) * VST + nt * 8 + g]);
                mma8(oacc[nt], a, b0, b1);
            }
        }

        // Prefetch tile kb+2 into stage (kb-1)%3 — idle since the top barrier.
        if (kb + 2 < nkb) issue(kb + 2);
        cp_commit();              // always commit: uniform group numbering
    }

    // Epilogue: O / l -> att[B*S, F]
    const float inv0 = 1.f / l_i[0];
    const float inv1 = 1.f / l_i[1];
#pragma unroll
    for (int nt = 0; nt < 8; nt++) {
        int c = h * DD + nt * 8 + 2 * tig;
        *(float2*)(att + (rb + qr0) * FF + c) =
            make_float2(oacc[nt][0] * inv0, oacc[nt][1] * inv0);
        *(float2*)(att + (rb + qr1) * FF + c) =
            make_float2(oacc[nt][2] * inv1, oacc[nt][3] * inv1);
    }
}

// ---------------------------------------------------------------------------
// Launch
// ---------------------------------------------------------------------------
extern "C" void kernel_launch(void* const* d_in, const int* in_sizes, int n_in,
                              void* d_out, int out_size)
{
    (void)in_sizes; (void)n_in; (void)out_size;
    const float*         x    = (const float*)d_in[0];
    const unsigned char* mask = (const unsigned char*)d_in[1];
    const float*         Wqkv = (const float*)d_in[2];
    const float*         bqkv = (const float*)d_in[3];
    const float*         Wout = (const float*)d_in[4];
    const float*         bout = (const float*)d_in[5];
    float*               out  = (float*)d_out;

    void* p;
    cudaGetSymbolAddress(&p, g_qkv);
    float* qkv = (float*)p;
    cudaGetSymbolAddress(&p, g_att);
    float* att = (float*)p;

    const int gsmem = 3 * GSTG * (int)sizeof(float);           // 56832
    const int asmem = (MSKOFF) * (int)sizeof(float) + 3 * 64;  // 142528
    cudaFuncSetAttribute(gemm_tf32_kernel,
                         cudaFuncAttributeMaxDynamicSharedMemorySize, gsmem);
    cudaFuncSetAttribute(attn_tf32_kernel,
                         cudaFuncAttributeMaxDynamicSharedMemorySize, asmem);

    // 1) QKV projection
    dim3 g1(NQKV / 128, MM / 128);   // (18, 64)
    gemm_tf32_kernel<<<g1, 256, gsmem>>>(x, Wqkv, bqkv, qkv, MM, NQKV, FF);

    // 2) Causal flash attention (tf32 MMA, cp.async pipeline)
    attn_tf32_kernel<<<dim3(SS / 128, HH, BB), 256, asmem>>>(qkv, mask, att);

    // 3) Output projection
    dim3 g2(FF / 128, MM / 128);     // (6, 64)
    gemm_tf32_kernel<<<g2, 256, gsmem>>>(att, Wout, bout, out, MM, FF, FF);
}

// round 13
// speedup vs baseline: 1.8527x; 1.2604x over previous
#include <cuda_runtime.h>
#include <math.h>
#include <stdint.h>

// Problem constants
#define BB 2
#define SS 4096
#define FF 768
#define HH 12
#define DD 64
#define MM (BB * SS)       // 8192
#define NQKV (3 * FF)      // 2304

// Scratch (allocation-free rule: __device__ globals)
__device__ float g_qkv[(size_t)MM * NQKV];   // [B*S, 3F] (tf32-valued)
__device__ float g_att[(size_t)MM * FF];     // xr for GEMM1, then attn out
__device__ float g_w1[(size_t)FF * NQKV];    // Wqkv rounded
__device__ float g_w2[(size_t)FF * FF];      // Wout rounded

// ---------------------------------------------------------------------------
// Helpers
// ---------------------------------------------------------------------------
__device__ __forceinline__ unsigned f2tf(float x) {   // round-to-nearest tf32
    unsigned u;
    asm("cvt.rna.tf32.f32 %0, %1;" : "=r"(u) : "f"(x));
    return u;
}
__device__ __forceinline__ float f2tff(float x) { return __uint_as_float(f2tf(x)); }
__device__ __forceinline__ float ex2(float x) {       // 2^x (MUFU.EX2)
    float y;
    asm("ex2.approx.f32 %0, %1;" : "=f"(y) : "f"(x));
    return y;
}
__device__ __forceinline__ void mma8(float d[4], const unsigned a[4],
                                     unsigned b0, unsigned b1) {
    asm volatile(
        "mma.sync.aligned.m16n8k8.row.col.f32.tf32.tf32.f32 "
        "{%0,%1,%2,%3},{%4,%5,%6,%7},{%8,%9},{%0,%1,%2,%3};"
        : "+f"(d[0]), "+f"(d[1]), "+f"(d[2]), "+f"(d[3])
        : "r"(a[0]), "r"(a[1]), "r"(a[2]), "r"(a[3]), "r"(b0), "r"(b1));
}
__device__ __forceinline__ void cpa16(uint32_t s, const void* g) {
    asm volatile("cp.async.cg.shared.global [%0], [%1], 16;" :: "r"(s), "l"(g));
}
__device__ __forceinline__ void cpa4(uint32_t s, const void* g) {
    asm volatile("cp.async.ca.shared.global [%0], [%1], 4;" :: "r"(s), "l"(g));
}
__device__ __forceinline__ void cp_commit() {
    asm volatile("cp.async.commit_group;");
}
template <int N>
__device__ __forceinline__ void cp_wait() {
    asm volatile("cp.async.wait_group %0;" :: "n"(N));
}

// ---------------------------------------------------------------------------
// Prep: round x, Wqkv, Wout to tf32 values once (HBM-bound, ~15us).
// After this, all GEMM/attention operands in gmem are already tf32-valued
// and the hot loops need no convert pass.
// ---------------------------------------------------------------------------
#define XN4  ((MM * FF) / 4)          // 1572864
#define W1N4 ((FF * NQKV) / 4)        // 442368
#define W2N4 ((FF * FF) / 4)          // 147456
__global__ __launch_bounds__(256) void round_prep_kernel(
    const float4* __restrict__ x,  float4* __restrict__ xr,
    const float4* __restrict__ w1, float4* __restrict__ w1r,
    const float4* __restrict__ w2, float4* __restrict__ w2r)
{
    const int stride = gridDim.x * blockDim.x;
    for (int i = blockIdx.x * blockDim.x + threadIdx.x; i < XN4; i += stride) {
        float4 v = x[i];
        v.x = f2tff(v.x); v.y = f2tff(v.y); v.z = f2tff(v.z); v.w = f2tff(v.w);
        xr[i] = v;
    }
    for (int i = blockIdx.x * blockDim.x + threadIdx.x; i < W1N4; i += stride) {
        float4 v = w1[i];
        v.x = f2tff(v.x); v.y = f2tff(v.y); v.z = f2tff(v.z); v.w = f2tff(v.w);
        w1r[i] = v;
    }
    for (int i = blockIdx.x * blockDim.x + threadIdx.x; i < W2N4; i += stride) {
        float4 v = w2[i];
        v.x = f2tff(v.x); v.y = f2tff(v.y); v.z = f2tff(v.z); v.w = f2tff(v.w);
        w2r[i] = v;
    }
}

// ---------------------------------------------------------------------------
// GEMM + bias, tf32 MMA, 3-stage cp.async pipeline, NO convert pass
// (operands pre-rounded in gmem). One __syncthreads per k-chunk.
// 128x128 CTA tile, 8 warps (4m x 2n), k-chunk 16.
// roundOut=1: round epilogue stores to tf32 values (for the qkv buffer).
// Dynamic smem: 3 * (128*20 + 16*136) * 4 = 56832 B.
// ---------------------------------------------------------------------------
#define GAST 20
#define GBST 136
#define GASZ (128 * GAST)
#define GBSZ (16 * GBST)
#define GSTG (GASZ + GBSZ)
__global__ __launch_bounds__(256, 2) void gemm_tf32_kernel(
    const float* __restrict__ A, const float* __restrict__ W,
    const float* __restrict__ bias, float* __restrict__ C,
    int M, int N, int K, int roundOut)
{
    extern __shared__ float gs[];
    const uint32_t sbase = (uint32_t)__cvta_generic_to_shared(gs);

    const int tid = threadIdx.x;
    const int wid = tid >> 5, lane = tid & 31;
    const int g = lane >> 2, tig = lane & 3;
    const int wm = (wid >> 1) * 32;
    const int wn = (wid & 1) * 64;
    const int row0 = blockIdx.y * 128;
    const int col0 = blockIdx.x * 128;

    auto issue = [&](int t) {
        const uint32_t sb = sbase + (uint32_t)((t % 3) * GSTG) * 4u;
#pragma unroll
        for (int l = 0; l < 2; l++) {
            int id = tid + l * 256;
            int ar = id >> 2, ac = id & 3;
            cpa16(sb + (uint32_t)(ar * GAST + ac * 4) * 4u,
                  A + (size_t)(row0 + ar) * K + t * 16 + ac * 4);
            int br = id >> 5, bc = id & 31;
            cpa16(sb + (uint32_t)(GASZ + br * GBST + bc * 4) * 4u,
                  W + (size_t)(t * 16 + br) * N + col0 + bc * 4);
        }
    };

    float acc[2][8][4];
#pragma unroll
    for (int mt = 0; mt < 2; mt++)
#pragma unroll
        for (int nt = 0; nt < 8; nt++)
#pragma unroll
            for (int c = 0; c < 4; c++) acc[mt][nt][c] = 0.f;

    const int nk = K >> 4;
    issue(0); cp_commit();
    if (nk > 1) issue(1);
    cp_commit();

    for (int ki = 0; ki < nk; ki++) {
        cp_wait<1>();          // tile ki landed (newest group = tile ki+1)
        __syncthreads();
        const int st = ki % 3;
        const float* ap = gs + st * GSTG;
        const float* bp = ap + GASZ;

#pragma unroll
        for (int ks = 0; ks < 16; ks += 8) {
            unsigned a[2][4];
#pragma unroll
            for (int mt = 0; mt < 2; mt++) {
                int rbse = wm + mt * 16;
                a[mt][0] = __float_as_uint(ap[(rbse + g) * GAST + ks + tig]);
                a[mt][1] = __float_as_uint(ap[(rbse + g + 8) * GAST + ks + tig]);
                a[mt][2] = __float_as_uint(ap[(rbse + g) * GAST + ks + tig + 4]);
                a[mt][3] = __float_as_uint(ap[(rbse + g + 8) * GAST + ks + tig + 4]);
            }
#pragma unroll
            for (int nt = 0; nt < 8; nt++) {
                unsigned b0 = __float_as_uint(bp[(ks + tig) * GBST + wn + nt * 8 + g]);
                unsigned b1 = __float_as_uint(bp[(ks + tig + 4) * GBST + wn + nt * 8 + g]);
                mma8(acc[0][nt], a[0], b0, b1);
                mma8(acc[1][nt], a[1], b0, b1);
            }
        }

        // Prefetch tile ki+2 into stage (ki-1)%3: its readers all passed the
        // barrier at the top of THIS iteration.
        if (ki + 2 < nk) issue(ki + 2);
        cp_commit();           // always commit: uniform group numbering
    }

#pragma unroll
    for (int mt = 0; mt < 2; mt++) {
        int r0 = row0 + wm + mt * 16 + g;
#pragma unroll
        for (int nt = 0; nt < 8; nt++) {
            int c = col0 + wn + nt * 8 + 2 * tig;
            float bx = bias[c], by = bias[c + 1];
            float2 v0 = make_float2(acc[mt][nt][0] + bx, acc[mt][nt][1] + by);
            float2 v1 = make_float2(acc[mt][nt][2] + bx, acc[mt][nt][3] + by);
            if (roundOut) {
                v0.x = f2tff(v0.x); v0.y = f2tff(v0.y);
                v1.x = f2tff(v1.x); v1.y = f2tff(v1.y);
            }
            *(float2*)(C + (size_t)r0 * N + c) = v0;
            *(float2*)(C + (size_t)(r0 + 8) * N + c) = v1;
        }
    }
}

// ---------------------------------------------------------------------------
// Flash attention, tf32 MMA. 2-stage cp.async K/V ring (one tile in flight,
// a full compute phase of latency cover), NO convert pass (qkv pre-rounded
// by the GEMM1 epilogue). Smem 106624 B -> 2 CTAs/SM (16 warps/SM).
// 128q x 64k blocks, 8 warps, warp owns m16 x n64. One __syncthreads/iter.
// K [key][d] stride 68, V [key][d] stride 72 (both conflict-free b-frags).
// Softmax in log2 domain (log2e folded into Q scale).
// ---------------------------------------------------------------------------
#define KST 68
#define VST 72
#define KSZ (64 * KST)
#define VSZ (64 * VST)
#define STG (KSZ + VSZ)          // 8960 floats per stage
#define PSOFF (2 * STG)
#define MSKOFF (PSOFF + 128 * 68)
__global__ __launch_bounds__(256, 2) void attn_tf32_kernel(
    const float* __restrict__ qkv, const unsigned char* __restrict__ mask,
    float* __restrict__ att)
{
    extern __shared__ float sm[];
    float* Ps = sm + PSOFF;                              // [128 q][68]
    unsigned char* msk = (unsigned char*)(sm + MSKOFF);  // 2 x 64
    const uint32_t sbase = (uint32_t)__cvta_generic_to_shared(sm);

    const int qb = gridDim.x - 1 - blockIdx.x;   // big blocks first (balance)
    const int h = blockIdx.y, b = blockIdx.z;
    const int tid = threadIdx.x;
    const int wid = tid >> 5, lane = tid & 31;
    const int g = lane >> 2, tig = lane & 3;
    const int m0 = wid * 16;
    const int q0 = qb * 128;
    const size_t rb = (size_t)b * SS;
    const int qr0 = q0 + m0 + g;
    const int qr1 = qr0 + 8;

    auto issue = [&](int kb) {   // K/V tile kb + mask -> stage kb%2
        const int s = kb & 1;
        const uint32_t sb = sbase + (uint32_t)(s * STG) * 4u;
        const float* base = qkv + (rb + (size_t)kb * 64) * NQKV + FF + h * DD;
#pragma unroll
        for (int l = 0; l < 4; l++) {
            int id = tid + l * 256;
            int r = id >> 4, c = id & 15;
            const float* kp = base + (size_t)r * NQKV + c * 4;
            cpa16(sb + (uint32_t)(r * KST + c * 4) * 4u, kp);
            cpa16(sb + (uint32_t)(KSZ + r * VST + c * 4) * 4u, kp + FF);  // V=K+F
        }
        if (tid < 16)
            cpa4(sbase + (uint32_t)MSKOFF * 4u + (uint32_t)(s * 64 + tid * 4),
                 mask + rb + (size_t)kb * 64 + tid * 4);
    };

    // Q fragments: qkv already tf32-valued; scale then re-round (<=1ulp).
    const float qscale = 0.125f * 1.44269504f;   // 1/sqrt(D) * log2(e)
    unsigned qf[8][4];
    {
        const float* p0 = qkv + (rb + qr0) * NQKV + h * DD;
        const float* p1 = p0 + (size_t)8 * NQKV;
#pragma unroll
        for (int kk = 0; kk < 8; kk++) {
            qf[kk][0] = f2tf(p0[kk * 8 + tig] * qscale);
            qf[kk][1] = f2tf(p1[kk * 8 + tig] * qscale);
            qf[kk][2] = f2tf(p0[kk * 8 + tig + 4] * qscale);
            qf[kk][3] = f2tf(p1[kk * 8 + tig + 4] * qscale);
        }
    }

    float m_i[2] = {-INFINITY, -INFINITY};
    float l_i[2] = {0.f, 0.f};
    float oacc[8][4];
#pragma unroll
    for (int nt = 0; nt < 8; nt++)
#pragma unroll
        for (int c = 0; c < 4; c++) oacc[nt][c] = 0.f;

    const int nkb = 2 * qb + 2;
    issue(0); cp_commit();

    for (int kb = 0; kb < nkb; kb++) {
        cp_wait<0>();             // tile kb landed (issued >=1 compute ago)
        __syncthreads();
        // Prefetch kb+1 into the other stage: its readers (iter kb-1) all
        // passed the barrier above. Lands during this iteration's compute.
        if (kb + 1 < nkb) issue(kb + 1);
        cp_commit();

        const int st = kb & 1;
        const float* ksp = sm + st * STG;
        const float* vsp = ksp + KSZ;
        const unsigned char* mp = msk + st * 64;
        const int k0 = kb * 64;

        // S = Q @ K^T
        float sacc[8][4];
#pragma unroll
        for (int nt = 0; nt < 8; nt++)
#pragma unroll
            for (int c = 0; c < 4; c++) sacc[nt][c] = 0.f;
#pragma unroll
        for (int kk = 0; kk < 8; kk++) {
#pragma unroll
            for (int nt = 0; nt < 8; nt++) {
                unsigned b0 = __float_as_uint(ksp[(nt * 8 + g) * KST + kk * 8 + tig]);
                unsigned b1 = __float_as_uint(ksp[(nt * 8 + g) * KST + kk * 8 + tig + 4]);
                mma8(sacc[nt], qf[kk], b0, b1);
            }
        }

        // Causal + padding masks
        const bool dcheck = (k0 + 63 > qr0);
#pragma unroll
        for (int nt = 0; nt < 8; nt++) {
            int c0 = k0 + nt * 8 + 2 * tig;
            bool p0 = mp[nt * 8 + 2 * tig] != 0;
            bool p1 = mp[nt * 8 + 2 * tig + 1] != 0;
            if (p0 || (dcheck && c0 > qr0))     sacc[nt][0] = -INFINITY;
            if (p1 || (dcheck && c0 + 1 > qr0)) sacc[nt][1] = -INFINITY;
            if (p0 || (dcheck && c0 > qr1))     sacc[nt][2] = -INFINITY;
            if (p1 || (dcheck && c0 + 1 > qr1)) sacc[nt][3] = -INFINITY;
        }

        // Online softmax in log2 domain (quad shuffles)
#pragma unroll
        for (int r = 0; r < 2; r++) {
            float mx = -INFINITY;
#pragma unroll
            for (int nt = 0; nt < 8; nt++)
                mx = fmaxf(mx, fmaxf(sacc[nt][2 * r], sacc[nt][2 * r + 1]));
            mx = fmaxf(mx, __shfl_xor_sync(0xffffffffu, mx, 1));
            mx = fmaxf(mx, __shfl_xor_sync(0xffffffffu, mx, 2));
            float mnew = fmaxf(m_i[r], mx);
            float alpha = ex2(m_i[r] - mnew);
            float sum = 0.f;
#pragma unroll
            for (int nt = 0; nt < 8; nt++) {
                float e0 = ex2(sacc[nt][2 * r] - mnew);
                float e1 = ex2(sacc[nt][2 * r + 1] - mnew);
                sacc[nt][2 * r] = e0;
                sacc[nt][2 * r + 1] = e1;
                sum += e0 + e1;
            }
            sum += __shfl_xor_sync(0xffffffffu, sum, 1);
            sum += __shfl_xor_sync(0xffffffffu, sum, 2);
            l_i[r] = l_i[r] * alpha + sum;
            m_i[r] = mnew;
#pragma unroll
            for (int nt = 0; nt < 8; nt++) {
                oacc[nt][2 * r] *= alpha;
                oacc[nt][2 * r + 1] *= alpha;
            }
        }

        // P bounce (tf32 at store): warp-private rows -> __syncwarp
#pragma unroll
        for (int nt = 0; nt < 8; nt++) {
            *(float2*)(Ps + (m0 + g) * 68 + nt * 8 + 2 * tig) =
                make_float2(f2tff(sacc[nt][0]), f2tff(sacc[nt][1]));
            *(float2*)(Ps + (m0 + g + 8) * 68 + nt * 8 + 2 * tig) =
                make_float2(f2tff(sacc[nt][2]), f2tff(sacc[nt][3]));
        }
        __syncwarp();

        // O += P @ V  (V is [key][d], stride 72)
#pragma unroll
        for (int kk = 0; kk < 8; kk++) {
            unsigned a[4];
            a[0] = __float_as_uint(Ps[(m0 + g) * 68 + kk * 8 + tig]);
            a[1] = __float_as_uint(Ps[(m0 + g + 8) * 68 + kk * 8 + tig]);
            a[2] = __float_as_uint(Ps[(m0 + g) * 68 + kk * 8 + tig + 4]);
            a[3] = __float_as_uint(Ps[(m0 + g + 8) * 68 + kk * 8 + tig + 4]);
#pragma unroll
            for (int nt = 0; nt < 8; nt++) {
                unsigned b0 = __float_as_uint(vsp[(kk * 8 + tig) * VST + nt * 8 + g]);
                unsigned b1 = __float_as_uint(vsp[(kk * 8 + tig + 4) * VST + nt * 8 + g]);
                mma8(oacc[nt], a, b0, b1);
            }
        }
    }

    // Epilogue: O / l, tf32-rounded (feeds the pre-rounded out-proj GEMM)
    const float inv0 = 1.f / l_i[0];
    const float inv1 = 1.f / l_i[1];
#pragma unroll
    for (int nt = 0; nt < 8; nt++) {
        int c = h * DD + nt * 8 + 2 * tig;
        *(float2*)(att + (rb + qr0) * FF + c) =
            make_float2(f2tff(oacc[nt][0] * inv0), f2tff(oacc[nt][1] * inv0));
        *(float2*)(att + (rb + qr1) * FF + c) =
            make_float2(f2tff(oacc[nt][2] * inv1), f2tff(oacc[nt][3] * inv1));
    }
}

// ---------------------------------------------------------------------------
// Launch
// ---------------------------------------------------------------------------
extern "C" void kernel_launch(void* const* d_in, const int* in_sizes, int n_in,
                              void* d_out, int out_size)
{
    (void)in_sizes; (void)n_in; (void)out_size;
    const float*         x    = (const float*)d_in[0];
    const unsigned char* mask = (const unsigned char*)d_in[1];
    const float*         Wqkv = (const float*)d_in[2];
    const float*         bqkv = (const float*)d_in[3];
    const float*         Wout = (const float*)d_in[4];
    const float*         bout = (const float*)d_in[5];
    float*               out  = (float*)d_out;

    void* p;
    cudaGetSymbolAddress(&p, g_qkv);  float* qkv = (float*)p;
    cudaGetSymbolAddress(&p, g_att);  float* att = (float*)p;
    cudaGetSymbolAddress(&p, g_w1);   float* w1r = (float*)p;
    cudaGetSymbolAddress(&p, g_w2);   float* w2r = (float*)p;

    const int gsmem = 3 * GSTG * (int)sizeof(float);            // 56832
    const int asmem = MSKOFF * (int)sizeof(float) + 2 * 64;     // 106624
    cudaFuncSetAttribute(gemm_tf32_kernel,
                         cudaFuncAttributeMaxDynamicSharedMemorySize, gsmem);
    cudaFuncSetAttribute(attn_tf32_kernel,
                         cudaFuncAttributeMaxDynamicSharedMemorySize, asmem);

    // 0) Round x, Wqkv, Wout to tf32 values (xr lives in g_att until attn)
    round_prep_kernel<<<2048, 256>>>(
        (const float4*)x,    (float4*)att,
        (const float4*)Wqkv, (float4*)w1r,
        (const float4*)Wout, (float4*)w2r);

    // 1) QKV projection (epilogue rounds output -> qkv is tf32-valued)
    dim3 g1(NQKV / 128, MM / 128);
    gemm_tf32_kernel<<<g1, 256, gsmem>>>(att, w1r, bqkv, qkv, MM, NQKV, FF, 1);

    // 2) Causal flash attention (overwrites g_att with rounded output)
    attn_tf32_kernel<<<dim3(SS / 128, HH, BB), 256, asmem>>>(qkv, mask, att);

    // 3) Output projection (no rounding on final output)
    dim3 g2(FF / 128, MM / 128);
    gemm_tf32_kernel<<<g2, 256, gsmem>>>(att, w2r, bout, out, MM, FF, FF, 0);
}

// round 15
// speedup vs baseline: 1.9714x; 1.0640x over previous
#include <cuda_runtime.h>
#include <math.h>
#include <stdint.h>

// Problem constants
#define BB 2
#define SS 4096
#define FF 768
#define HH 12
#define DD 64
#define MM (BB * SS)       // 8192
#define NQKV (3 * FF)      // 2304

// Scratch (allocation-free rule: __device__ globals)
__device__ float g_qkv[(size_t)MM * NQKV];   // [B*S, 3F] (tf32-valued)
__device__ float g_att[(size_t)MM * FF];     // xr for GEMM1, then attn out
__device__ float g_w1[(size_t)FF * NQKV];    // Wqkv rounded
__device__ float g_w2[(size_t)FF * FF];      // Wout rounded

// ---------------------------------------------------------------------------
// Helpers
// ---------------------------------------------------------------------------
__device__ __forceinline__ unsigned f2tf(float x) {   // round-to-nearest tf32
    unsigned u;
    asm("cvt.rna.tf32.f32 %0, %1;" : "=r"(u) : "f"(x));
    return u;
}
__device__ __forceinline__ float f2tff(float x) { return __uint_as_float(f2tf(x)); }
__device__ __forceinline__ float ex2(float x) {       // 2^x (MUFU.EX2)
    float y;
    asm("ex2.approx.f32 %0, %1;" : "=f"(y) : "f"(x));
    return y;
}
__device__ __forceinline__ void mma8(float d[4], const unsigned a[4],
                                     unsigned b0, unsigned b1) {
    asm volatile(
        "mma.sync.aligned.m16n8k8.row.col.f32.tf32.tf32.f32 "
        "{%0,%1,%2,%3},{%4,%5,%6,%7},{%8,%9},{%0,%1,%2,%3};"
        : "+f"(d[0]), "+f"(d[1]), "+f"(d[2]), "+f"(d[3])
        : "r"(a[0]), "r"(a[1]), "r"(a[2]), "r"(a[3]), "r"(b0), "r"(b1));
}
__device__ __forceinline__ void cpa16(uint32_t s, const void* g) {
    asm volatile("cp.async.cg.shared.global [%0], [%1], 16;" :: "r"(s), "l"(g));
}
__device__ __forceinline__ void cpa4(uint32_t s, const void* g) {
    asm volatile("cp.async.ca.shared.global [%0], [%1], 4;" :: "r"(s), "l"(g));
}
__device__ __forceinline__ void cp_commit() {
    asm volatile("cp.async.commit_group;");
}
template <int N>
__device__ __forceinline__ void cp_wait() {
    asm volatile("cp.async.wait_group %0;" :: "n"(N));
}

// ---------------------------------------------------------------------------
// Prep: round x, Wqkv, Wout to tf32 values once (HBM-bound, ~25us).
// ---------------------------------------------------------------------------
#define XN4  ((MM * FF) / 4)
#define W1N4 ((FF * NQKV) / 4)
#define W2N4 ((FF * FF) / 4)
__global__ __launch_bounds__(256) void round_prep_kernel(
    const float4* __restrict__ x,  float4* __restrict__ xr,
    const float4* __restrict__ w1, float4* __restrict__ w1r,
    const float4* __restrict__ w2, float4* __restrict__ w2r)
{
    const int stride = gridDim.x * blockDim.x;
    for (int i = blockIdx.x * blockDim.x + threadIdx.x; i < XN4; i += stride) {
        float4 v = x[i];
        v.x = f2tff(v.x); v.y = f2tff(v.y); v.z = f2tff(v.z); v.w = f2tff(v.w);
        xr[i] = v;
    }
    for (int i = blockIdx.x * blockDim.x + threadIdx.x; i < W1N4; i += stride) {
        float4 v = w1[i];
        v.x = f2tff(v.x); v.y = f2tff(v.y); v.z = f2tff(v.z); v.w = f2tff(v.w);
        w1r[i] = v;
    }
    for (int i = blockIdx.x * blockDim.x + threadIdx.x; i < W2N4; i += stride) {
        float4 v = w2[i];
        v.x = f2tff(v.x); v.y = f2tff(v.y); v.z = f2tff(v.z); v.w = f2tff(v.w);
        w2r[i] = v;
    }
}

// ---------------------------------------------------------------------------
// GEMM + bias, tf32 MMA, 3-stage cp.async pipeline, k-chunk 32 (one barrier
// per 128 MMAs). Operands pre-rounded in gmem -> no convert pass.
// 128x128 CTA tile, 8 warps (4m x 2n).
// A [128][36] (36%32==4 -> 8-row fragment groups conflict-free),
// B [32][136] (136%32==8 -> conflict-free as before).
// Dynamic smem: 3 * (128*36 + 32*136) * 4 = 107520 B; occ 2 (215KB < 228KB).
// ---------------------------------------------------------------------------
#define GAST 36
#define GBST 136
#define GASZ (128 * GAST)        // 4608 floats
#define GBSZ (32 * GBST)         // 4352 floats
#define GSTG (GASZ + GBSZ)       // 8960 floats per stage
__global__ __launch_bounds__(256, 2) void gemm_tf32_kernel(
    const float* __restrict__ A, const float* __restrict__ W,
    const float* __restrict__ bias, float* __restrict__ C,
    int M, int N, int K, int roundOut)
{
    extern __shared__ float gs[];
    const uint32_t sbase = (uint32_t)__cvta_generic_to_shared(gs);

    const int tid = threadIdx.x;
    const int wid = tid >> 5, lane = tid & 31;
    const int g = lane >> 2, tig = lane & 3;
    const int wm = (wid >> 1) * 32;
    const int wn = (wid & 1) * 64;
    const int row0 = blockIdx.y * 128;
    const int col0 = blockIdx.x * 128;

    auto issue = [&](int t) {    // k-chunk t (32 wide) -> stage t%3
        const uint32_t sb = sbase + (uint32_t)((t % 3) * GSTG) * 4u;
#pragma unroll
        for (int l = 0; l < 4; l++) {
            int id = tid + l * 256;          // 0..1023
            int ar = id >> 3, ac = id & 7;   // A: 128 rows x 8 float4
            cpa16(sb + (uint32_t)(ar * GAST + ac * 4) * 4u,
                  A + (size_t)(row0 + ar) * K + t * 32 + ac * 4);
            int br = id >> 5, bc = id & 31;  // B: 32 rows x 32 float4
            cpa16(sb + (uint32_t)(GASZ + br * GBST + bc * 4) * 4u,
                  W + (size_t)(t * 32 + br) * N + col0 + bc * 4);
        }
    };

    float acc[2][8][4];
#pragma unroll
    for (int mt = 0; mt < 2; mt++)
#pragma unroll
        for (int nt = 0; nt < 8; nt++)
#pragma unroll
            for (int c = 0; c < 4; c++) acc[mt][nt][c] = 0.f;

    const int nk = K >> 5;       // 24 for K=768
    issue(0); cp_commit();
    if (nk > 1) issue(1);
    cp_commit();

    for (int ki = 0; ki < nk; ki++) {
        cp_wait<1>();            // chunk ki landed
        __syncthreads();
        const int st = ki % 3;
        const float* ap = gs + st * GSTG;
        const float* bp = ap + GASZ;

#pragma unroll
        for (int ks = 0; ks < 32; ks += 8) {
            unsigned a[2][4];
#pragma unroll
            for (int mt = 0; mt < 2; mt++) {
                int rbse = wm + mt * 16;
                a[mt][0] = __float_as_uint(ap[(rbse + g) * GAST + ks + tig]);
                a[mt][1] = __float_as_uint(ap[(rbse + g + 8) * GAST + ks + tig]);
                a[mt][2] = __float_as_uint(ap[(rbse + g) * GAST + ks + tig + 4]);
                a[mt][3] = __float_as_uint(ap[(rbse + g + 8) * GAST + ks + tig + 4]);
            }
#pragma unroll
            for (int nt = 0; nt < 8; nt++) {
                unsigned b0 = __float_as_uint(bp[(ks + tig) * GBST + wn + nt * 8 + g]);
                unsigned b1 = __float_as_uint(bp[(ks + tig + 4) * GBST + wn + nt * 8 + g]);
                mma8(acc[0][nt], a[0], b0, b1);
                mma8(acc[1][nt], a[1], b0, b1);
            }
        }

        if (ki + 2 < nk) issue(ki + 2);   // stage (ki-1)%3: readers passed top barrier
        cp_commit();                      // uniform group numbering
    }

#pragma unroll
    for (int mt = 0; mt < 2; mt++) {
        int r0 = row0 + wm + mt * 16 + g;
#pragma unroll
        for (int nt = 0; nt < 8; nt++) {
            int c = col0 + wn + nt * 8 + 2 * tig;
            float bx = bias[c], by = bias[c + 1];
            float2 v0 = make_float2(acc[mt][nt][0] + bx, acc[mt][nt][1] + by);
            float2 v1 = make_float2(acc[mt][nt][2] + bx, acc[mt][nt][3] + by);
            if (roundOut) {
                v0.x = f2tff(v0.x); v0.y = f2tff(v0.y);
                v1.x = f2tff(v1.x); v1.y = f2tff(v1.y);
            }
            *(float2*)(C + (size_t)r0 * N + c) = v0;
            *(float2*)(C + (size_t)(r0 + 8) * N + c) = v1;
        }
    }
}

// ---------------------------------------------------------------------------
// Flash attention, tf32 MMA, 2-stage cp.async K/V ring, occ 2.
// New this round:
//  - anyPad fast path: one uniform 64-byte OR per tile; when clear,
//    non-diagonal blocks do ZERO masking work.
//  - diagonal skip: warps whose query rows are entirely below the key block
//    (fully causally masked) skip MMA+softmax for that block.
// ---------------------------------------------------------------------------
#define KST 68
#define VST 72
#define KSZ (64 * KST)
#define VSZ (64 * VST)
#define STG (KSZ + VSZ)
#define PSOFF (2 * STG)
#define MSKOFF (PSOFF + 128 * 68)
__global__ __launch_bounds__(256, 2) void attn_tf32_kernel(
    const float* __restrict__ qkv, const unsigned char* __restrict__ mask,
    float* __restrict__ att)
{
    extern __shared__ float sm[];
    float* Ps = sm + PSOFF;
    unsigned char* msk = (unsigned char*)(sm + MSKOFF);  // 2 x 64
    const uint32_t sbase = (uint32_t)__cvta_generic_to_shared(sm);

    const int qb = gridDim.x - 1 - blockIdx.x;
    const int h = blockIdx.y, b = blockIdx.z;
    const int tid = threadIdx.x;
    const int wid = tid >> 5, lane = tid & 31;
    const int g = lane >> 2, tig = lane & 3;
    const int m0 = wid * 16;
    const int q0 = qb * 128;
    const size_t rb = (size_t)b * SS;
    const int qr0 = q0 + m0 + g;
    const int qr1 = qr0 + 8;

    auto issue = [&](int kb) {
        const int s = kb & 1;
        const uint32_t sb = sbase + (uint32_t)(s * STG) * 4u;
        const float* base = qkv + (rb + (size_t)kb * 64) * NQKV + FF + h * DD;
#pragma unroll
        for (int l = 0; l < 4; l++) {
            int id = tid + l * 256;
            int r = id >> 4, c = id & 15;
            const float* kp = base + (size_t)r * NQKV + c * 4;
            cpa16(sb + (uint32_t)(r * KST + c * 4) * 4u, kp);
            cpa16(sb + (uint32_t)(KSZ + r * VST + c * 4) * 4u, kp + FF);
        }
        if (tid < 16)
            cpa4(sbase + (uint32_t)MSKOFF * 4u + (uint32_t)(s * 64 + tid * 4),
                 mask + rb + (size_t)kb * 64 + tid * 4);
    };

    // Q fragments (qkv already tf32-valued; scale then re-round)
    const float qscale = 0.125f * 1.44269504f;
    unsigned qf[8][4];
    {
        const float* p0 = qkv + (rb + qr0) * NQKV + h * DD;
        const float* p1 = p0 + (size_t)8 * NQKV;
#pragma unroll
        for (int kk = 0; kk < 8; kk++) {
            qf[kk][0] = f2tf(p0[kk * 8 + tig] * qscale);
            qf[kk][1] = f2tf(p1[kk * 8 + tig] * qscale);
            qf[kk][2] = f2tf(p0[kk * 8 + tig + 4] * qscale);
            qf[kk][3] = f2tf(p1[kk * 8 + tig + 4] * qscale);
        }
    }

    float m_i[2] = {-INFINITY, -INFINITY};
    float l_i[2] = {0.f, 0.f};
    float oacc[8][4];
#pragma unroll
    for (int nt = 0; nt < 8; nt++)
#pragma unroll
        for (int c = 0; c < 4; c++) oacc[nt][c] = 0.f;

    const int nkb = 2 * qb + 2;
    issue(0); cp_commit();

    for (int kb = 0; kb < nkb; kb++) {
        cp_wait<0>();
        __syncthreads();
        if (kb + 1 < nkb) issue(kb + 1);
        cp_commit();

        const int st = kb & 1;
        const float* ksp = sm + st * STG;
        const float* vsp = ksp + KSZ;
        const unsigned char* mp = msk + st * 64;
        const int k0 = kb * 64;

        // Warp-uniform skip: this warp's rows all precede the whole key block.
        if (k0 > q0 + m0 + 15) continue;   // barriers/issue already done above

        // S = Q @ K^T
        float sacc[8][4];
#pragma unroll
        for (int nt = 0; nt < 8; nt++)
#pragma unroll
            for (int c = 0; c < 4; c++) sacc[nt][c] = 0.f;
#pragma unroll
        for (int kk = 0; kk < 8; kk++) {
#pragma unroll
            for (int nt = 0; nt < 8; nt++) {
                unsigned b0 = __float_as_uint(ksp[(nt * 8 + g) * KST + kk * 8 + tig]);
                unsigned b1 = __float_as_uint(ksp[(nt * 8 + g) * KST + kk * 8 + tig + 4]);
                mma8(sacc[nt], qf[kk], b0, b1);
            }
        }

        // Uniform padding probe (4 LDS.128 + ORs); skips the per-element
        // padding path entirely when the tile has no padded keys.
        const uint4* m4 = (const uint4*)mp;
        uint4 w0 = m4[0], w1 = m4[1], w2 = m4[2], w3 = m4[3];
        unsigned orv = (w0.x | w0.y | w0.z | w0.w) | (w1.x | w1.y | w1.z | w1.w)
                     | (w2.x | w2.y | w2.z | w2.w) | (w3.x | w3.y | w3.z | w3.w);
        const bool dcheck = (k0 + 63 > qr0);

        if (orv != 0) {          // rare: full padding + causal path
#pragma unroll
            for (int nt = 0; nt < 8; nt++) {
                int c0 = k0 + nt * 8 + 2 * tig;
                bool p0 = mp[nt * 8 + 2 * tig] != 0;
                bool p1 = mp[nt * 8 + 2 * tig + 1] != 0;
                if (p0 || (dcheck && c0 > qr0))     sacc[nt][0] = -INFINITY;
                if (p1 || (dcheck && c0 + 1 > qr0)) sacc[nt][1] = -INFINITY;
                if (p0 || (dcheck && c0 > qr1))     sacc[nt][2] = -INFINITY;
                if (p1 || (dcheck && c0 + 1 > qr1)) sacc[nt][3] = -INFINITY;
            }
        } else if (dcheck) {     // diagonal block, causal only
#pragma unroll
            for (int nt = 0; nt < 8; nt++) {
                int c0 = k0 + nt * 8 + 2 * tig;
                if (c0 > qr0)     sacc[nt][0] = -INFINITY;
                if (c0 + 1 > qr0) sacc[nt][1] = -INFINITY;
                if (c0 > qr1)     sacc[nt][2] = -INFINITY;
                if (c0 + 1 > qr1) sacc[nt][3] = -INFINITY;
            }
        }
        // else: fully visible, no masking work at all.

        // Online softmax in log2 domain (quad shuffles)
#pragma unroll
        for (int r = 0; r < 2; r++) {
            float mx = -INFINITY;
#pragma unroll
            for (int nt = 0; nt < 8; nt++)
                mx = fmaxf(mx, fmaxf(sacc[nt][2 * r], sacc[nt][2 * r + 1]));
            mx = fmaxf(mx, __shfl_xor_sync(0xffffffffu, mx, 1));
            mx = fmaxf(mx, __shfl_xor_sync(0xffffffffu, mx, 2));
            float mnew = fmaxf(m_i[r], mx);
            float alpha = ex2(m_i[r] - mnew);
            float sum = 0.f;
#pragma unroll
            for (int nt = 0; nt < 8; nt++) {
                float e0 = ex2(sacc[nt][2 * r] - mnew);
                float e1 = ex2(sacc[nt][2 * r + 1] - mnew);
                sacc[nt][2 * r] = e0;
                sacc[nt][2 * r + 1] = e1;
                sum += e0 + e1;
            }
            sum += __shfl_xor_sync(0xffffffffu, sum, 1);
            sum += __shfl_xor_sync(0xffffffffu, sum, 2);
            l_i[r] = l_i[r] * alpha + sum;
            m_i[r] = mnew;
#pragma unroll
            for (int nt = 0; nt < 8; nt++) {
                oacc[nt][2 * r] *= alpha;
                oacc[nt][2 * r + 1] *= alpha;
            }
        }

        // P bounce (tf32 at store): warp-private rows -> __syncwarp
#pragma unroll
        for (int nt = 0; nt < 8; nt++) {
            *(float2*)(Ps + (m0 + g) * 68 + nt * 8 + 2 * tig) =
                make_float2(f2tff(sacc[nt][0]), f2tff(sacc[nt][1]));
            *(float2*)(Ps + (m0 + g + 8) * 68 + nt * 8 + 2 * tig) =
                make_float2(f2tff(sacc[nt][2]), f2tff(sacc[nt][3]));
        }
        __syncwarp();

        // O += P @ V
#pragma unroll
        for (int kk = 0; kk < 8; kk++) {
            unsigned a[4];
            a[0] = __float_as_uint(Ps[(m0 + g) * 68 + kk * 8 + tig]);
            a[1] = __float_as_uint(Ps[(m0 + g + 8) * 68 + kk * 8 + tig]);
            a[2] = __float_as_uint(Ps[(m0 + g) * 68 + kk * 8 + tig + 4]);
            a[3] = __float_as_uint(Ps[(m0 + g + 8) * 68 + kk * 8 + tig + 4]);
#pragma unroll
            for (int nt = 0; nt < 8; nt++) {
                unsigned b0 = __float_as_uint(vsp[(kk * 8 + tig) * VST + nt * 8 + g]);
                unsigned b1 = __float_as_uint(vsp[(kk * 8 + tig + 4) * VST + nt * 8 + g]);
                mma8(oacc[nt], a, b0, b1);
            }
        }
    }

    // Epilogue: O / l, tf32-rounded (feeds the pre-rounded out-proj GEMM)
    const float inv0 = 1.f / l_i[0];
    const float inv1 = 1.f / l_i[1];
#pragma unroll
    for (int nt = 0; nt < 8; nt++) {
        int c = h * DD + nt * 8 + 2 * tig;
        *(float2*)(att + (rb + qr0) * FF + c) =
            make_float2(f2tff(oacc[nt][0] * inv0), f2tff(oacc[nt][1] * inv0));
        *(float2*)(att + (rb + qr1) * FF + c) =
            make_float2(f2tff(oacc[nt][2] * inv1), f2tff(oacc[nt][3] * inv1));
    }
}

// ---------------------------------------------------------------------------
// Launch
// ---------------------------------------------------------------------------
extern "C" void kernel_launch(void* const* d_in, const int* in_sizes, int n_in,
                              void* d_out, int out_size)
{
    (void)in_sizes; (void)n_in; (void)out_size;
    const float*         x    = (const float*)d_in[0];
    const unsigned char* mask = (const unsigned char*)d_in[1];
    const float*         Wqkv = (const float*)d_in[2];
    const float*         bqkv = (const float*)d_in[3];
    const float*         Wout = (const float*)d_in[4];
    const float*         bout = (const float*)d_in[5];
    float*               out  = (float*)d_out;

    void* p;
    cudaGetSymbolAddress(&p, g_qkv);  float* qkv = (float*)p;
    cudaGetSymbolAddress(&p, g_att);  float* att = (float*)p;
    cudaGetSymbolAddress(&p, g_w1);   float* w1r = (float*)p;
    cudaGetSymbolAddress(&p, g_w2);   float* w2r = (float*)p;

    const int gsmem = 3 * GSTG * (int)sizeof(float);            // 107520
    const int asmem = MSKOFF * (int)sizeof(float) + 2 * 64;     // 106624
    cudaFuncSetAttribute(gemm_tf32_kernel,
                         cudaFuncAttributeMaxDynamicSharedMemorySize, gsmem);
    cudaFuncSetAttribute(attn_tf32_kernel,
                         cudaFuncAttributeMaxDynamicSharedMemorySize, asmem);

    // 0) Round x, Wqkv, Wout to tf32 values (xr parked in g_att)
    round_prep_kernel<<<2048, 256>>>(
        (const float4*)x,    (float4*)att,
        (const float4*)Wqkv, (float4*)w1r,
        (const float4*)Wout, (float4*)w2r);

    // 1) QKV projection (epilogue rounds -> qkv tf32-valued)
    dim3 g1(NQKV / 128, MM / 128);
    gemm_tf32_kernel<<<g1, 256, gsmem>>>(att, w1r, bqkv, qkv, MM, NQKV, FF, 1);

    // 2) Causal flash attention
    attn_tf32_kernel<<<dim3(SS / 128, HH, BB), 256, asmem>>>(qkv, mask, att);

    // 3) Output projection
    dim3 g2(FF / 128, MM / 128);
    gemm_tf32_kernel<<<g2, 256, gsmem>>>(att, w2r, bout, out, MM, FF, FF, 0);
}